// round 4
// baseline (speedup 1.0000x reference)
#include <cuda_runtime.h>
#include <cstdint>

// out = (x != corner_of_plane) ? 1.0f : 0.0f
// x: (16, 3, 1024, 1024) fp32, plane = 1<<20 elements.
// HBM-streaming. Reads: __ldcs (evict-first, zero reuse). Stores: default .wb
// so L2 coalesces writebacks into bursts -> fewer HBM R/W turnarounds.

#define THREADS 256
#define UNROLL 4

__global__ void __launch_bounds__(THREADS) remover_kernel(
    const float* __restrict__ x,
    float* __restrict__ out) {

    const float4* __restrict__ x4 = reinterpret_cast<const float4*>(x);
    float4* __restrict__ out4 = reinterpret_cast<float4*>(out);

    long long base = (long long)blockIdx.x * (THREADS * UNROLL) + threadIdx.x;

    // Block tile (1024 float4s) always lies within one plane (262144 float4s).
    // plane = element_idx >> 20 = float4_idx >> 18 — uniform across the block.
    long long plane = ((long long)blockIdx.x * (THREADS * UNROLL)) >> 18;
    float corner = __ldg(x + (plane << 20));

    float4 v[UNROLL];
#pragma unroll
    for (int u = 0; u < UNROLL; u++) {
        v[u] = __ldcs(x4 + base + (long long)u * THREADS);
    }

#pragma unroll
    for (int u = 0; u < UNROLL; u++) {
        float4 r;
        r.x = (v[u].x != corner) ? 1.0f : 0.0f;
        r.y = (v[u].y != corner) ? 1.0f : 0.0f;
        r.z = (v[u].z != corner) ? 1.0f : 0.0f;
        r.w = (v[u].w != corner) ? 1.0f : 0.0f;
        out4[base + (long long)u * THREADS] = r;   // default .wb store
    }
}

extern "C" void kernel_launch(void* const* d_in, const int* in_sizes, int n_in,
                              void* d_out, int out_size) {
    const float* x = (const float*)d_in[0];
    float* out = (float*)d_out;

    long long n = (long long)in_sizes[0];                 // 50331648
    long long n4 = n >> 2;                                // 12582912 float4s
    long long per_block = (long long)THREADS * UNROLL;    // 1024 float4s
    long long blocks = (n4 + per_block - 1) / per_block;  // 12288, exact fit

    remover_kernel<<<(unsigned)blocks, THREADS>>>(x, out);
}

// round 5
// speedup vs baseline: 1.0070x; 1.0070x over previous
#include <cuda_runtime.h>
#include <cstdint>

// out = (x != corner_of_plane) ? 1.0f : 0.0f
// x: (16, 3, 1024, 1024) fp32, plane = 1<<20 elements.
// HBM-streaming. Reads: __ldcs (evict-first, zero reuse).
// Stores: __stwt (write-through) — no dirty L2 state at kernel end, so the
// graph-replay steady state has no writeback burst colliding with the next
// iteration's read stream.

#define THREADS 256
#define UNROLL 4

__global__ void __launch_bounds__(THREADS) remover_kernel(
    const float* __restrict__ x,
    float* __restrict__ out) {

    const float4* __restrict__ x4 = reinterpret_cast<const float4*>(x);
    float4* __restrict__ out4 = reinterpret_cast<float4*>(out);

    long long base = (long long)blockIdx.x * (THREADS * UNROLL) + threadIdx.x;

    // Block tile (1024 float4s) always lies within one plane (262144 float4s).
    // plane = element_idx >> 20 = float4_idx >> 18 — uniform across the block.
    long long plane = ((long long)blockIdx.x * (THREADS * UNROLL)) >> 18;
    float corner = __ldg(x + (plane << 20));

    float4 v[UNROLL];
#pragma unroll
    for (int u = 0; u < UNROLL; u++) {
        v[u] = __ldcs(x4 + base + (long long)u * THREADS);
    }

#pragma unroll
    for (int u = 0; u < UNROLL; u++) {
        float4 r;
        r.x = (v[u].x != corner) ? 1.0f : 0.0f;
        r.y = (v[u].y != corner) ? 1.0f : 0.0f;
        r.z = (v[u].z != corner) ? 1.0f : 0.0f;
        r.w = (v[u].w != corner) ? 1.0f : 0.0f;
        __stwt(out4 + base + (long long)u * THREADS, r);   // write-through
    }
}

extern "C" void kernel_launch(void* const* d_in, const int* in_sizes, int n_in,
                              void* d_out, int out_size) {
    const float* x = (const float*)d_in[0];
    float* out = (float*)d_out;

    long long n = (long long)in_sizes[0];                 // 50331648
    long long n4 = n >> 2;                                // 12582912 float4s
    long long per_block = (long long)THREADS * UNROLL;    // 1024 float4s
    long long blocks = (n4 + per_block - 1) / per_block;  // 12288, exact fit

    remover_kernel<<<(unsigned)blocks, THREADS>>>(x, out);
}